// round 7
// baseline (speedup 1.0000x reference)
#include <cuda_runtime.h>
#include <cstdint>

// ----------------------------------------------------------------------------
// Polynormer forward: N=100000, E=1.6M, D=256, H=4, C=64, L=3, OUT=64
// R7: GEMM grid axes swapped (segments on x, row-tiles on y) so one wave
//     touches all 6 weight-segments of the same A tiles -> A read from DRAM
//     once instead of ~6x (ncu showed 885MB DRAM vs 410MB compulsory).
// ----------------------------------------------------------------------------

#define NN 100000
#define EE 1600000
#define DD 256
#define HH 4
#define OUTD 64
#define NEG_SLOPE 0.2f
#define LNEPS 1e-5f

// ---------------- scratch (device globals; allocation-free) -----------------
__device__ float g_x   [NN * DD];
__device__ float g_h   [NN * DD];
__device__ float g_hg  [NN * DD];
__device__ float g_xl  [NN * DD];
__device__ float g_xloc[NN * DD];
__device__ float g_wr  [3 * 196608];      // tf32-rounded Wh|Wg|Wl
__device__ float g_asrc[NN * HH];
__device__ float g_adst[NN * HH];
__device__ int   g_cnt   [NN];
__device__ int   g_rowptr[NN + 1];
__device__ int   g_cursor[NN];
__device__ int   g_srcs  [EE + NN];
__device__ int   g_bsum[128];
__device__ int   g_boff[128];

static inline int cdiv(int a, int b) { return (a + b - 1) / b; }

__device__ __forceinline__ uint32_t f2tf32(float f) {
    uint32_t u;
    asm("cvt.rna.tf32.f32 %0, %1;" : "=r"(u) : "f"(f));
    return u;
}

// ---------------- CSR build --------------------------------------------------
__global__ void k_init_cnt() {
    int i = blockIdx.x * blockDim.x + threadIdx.x;
    if (i < NN) g_cnt[i] = 1;  // self loop
}

__global__ void k_hist(const int* __restrict__ ei) {
    int i = blockIdx.x * blockDim.x + threadIdx.x;
    if (i < EE) atomicAdd(&g_cnt[ei[EE + i]], 1);
}

__global__ void k_scan1() {
    __shared__ int sh[1024];
    int t = threadIdx.x, b = blockIdx.x;
    int idx = b * 1024 + t;
    int v = (idx < NN) ? g_cnt[idx] : 0;
    sh[t] = v;
    for (int off = 1; off < 1024; off <<= 1) {
        __syncthreads();
        int u = (t >= off) ? sh[t - off] : 0;
        __syncthreads();
        sh[t] += u;
    }
    if (idx < NN) g_rowptr[idx + 1] = sh[t];
    if (t == 1023) g_bsum[b] = sh[t];
}

__global__ void k_scan2(int nb) {
    if (threadIdx.x == 0 && blockIdx.x == 0) {
        int acc = 0;
        for (int i = 0; i < nb; i++) { g_boff[i] = acc; acc += g_bsum[i]; }
    }
}

__global__ void k_scan3() {
    int idx = blockIdx.x * blockDim.x + threadIdx.x;
    if (idx == 0) { g_rowptr[0] = 0; g_cursor[0] = 0; }
    if (idx < NN) {
        int v = g_rowptr[idx + 1] + g_boff[idx >> 10];
        g_rowptr[idx + 1] = v;
        if (idx + 1 < NN) g_cursor[idx + 1] = v;
    }
}

__global__ void k_scatter(const int* __restrict__ ei) {
    int idx = blockIdx.x * blockDim.x + threadIdx.x;
    int src, dst;
    if (idx < EE)            { src = ei[idx]; dst = ei[EE + idx]; }
    else if (idx < EE + NN)  { src = idx - EE; dst = src; }
    else return;
    int pos = atomicAdd(&g_cursor[dst], 1);
    g_srcs[pos] = src;
}

// ---------------- weight pre-round to tf32 ----------------------------------
__global__ void k_round(const float* __restrict__ Wh, const float* __restrict__ Wg,
                        const float* __restrict__ Wl) {
    int i = blockIdx.x * blockDim.x + threadIdx.x;    // float4 index
    if (i >= 147456) return;
    const float* src = (i < 49152) ? Wh : (i < 98304 ? Wg : Wl);
    int off = (i % 49152) * 4;
    float4 v = *(const float4*)&src[off];
    float4 o;
    o.x = __uint_as_float(f2tf32(v.x));
    o.y = __uint_as_float(f2tf32(v.y));
    o.z = __uint_as_float(f2tf32(v.z));
    o.w = __uint_as_float(f2tf32(v.w));
    *(float4*)&g_wr[i * 4] = o;
}

// ---------------- MMA primitives ---------------------------------------------
#define GBM 128
#define GBN 128
#define GBK 16

__device__ __forceinline__ void mma_tf32(float* d, const uint32_t* a, const uint32_t* b) {
    asm volatile(
        "mma.sync.aligned.m16n8k8.row.col.f32.tf32.tf32.f32 "
        "{%0,%1,%2,%3}, {%4,%5,%6,%7}, {%8,%9}, {%0,%1,%2,%3};\n"
        : "+f"(d[0]), "+f"(d[1]), "+f"(d[2]), "+f"(d[3])
        : "r"(a[0]), "r"(a[1]), "r"(a[2]), "r"(a[3]), "r"(b[0]), "r"(b[1]));
}

__device__ __forceinline__ void cpa16(uint32_t sa, const void* g, bool p) {
    int sz = p ? 16 : 0;
    asm volatile("cp.async.cg.shared.global [%0], [%1], 16, %2;\n"
                 :: "r"(sa), "l"(g), "r"(sz) : "memory");
}
#define CP_COMMIT() asm volatile("cp.async.commit_group;\n" ::: "memory")
#define CP_WAIT1()  asm volatile("cp.async.wait_group 1;\n" ::: "memory")

// ---------------- legacy GEMM (cvt path) for input/output GEMMs --------------
// grid: (col tiles, row tiles)  — row tiles on Y for L2 reuse of A
template <bool RELU, bool BIAS, bool ROUND>
__global__ void __launch_bounds__(256, 2) k_mma(
    const float* __restrict__ A, const float* __restrict__ B,
    const float* __restrict__ bias, float* __restrict__ C,
    int M, int K, int Nc)
{
    __shared__ uint32_t As[2][GBM][GBK + 4];
    __shared__ uint32_t Bs[2][GBK][GBN + 8];

    int tid  = threadIdx.x;
    int lane = tid & 31;
    int warp = tid >> 5;
    int wr = warp >> 2, wc = warp & 3;
    int lr = lane >> 2, lc = lane & 3;
    int rowBase = blockIdx.y * GBM;
    int colBase = blockIdx.x * GBN;

    int aRow = tid >> 1;
    int aK   = (tid & 1) << 3;
    int bRow = tid >> 4;
    int bCol = (tid & 15) << 3;

    float acc[4][4][4];
#pragma unroll
    for (int m = 0; m < 4; m++)
#pragma unroll
        for (int n = 0; n < 4; n++)
#pragma unroll
            for (int r = 0; r < 4; r++) acc[m][n][r] = 0.f;

    float aReg[8], bReg[8];
    const int NT = K / GBK;

    {
        bool okA = (rowBase + aRow) < M;
        const float* pA = A + (size_t)(rowBase + aRow) * K + aK;
        float4 v0 = okA ? *(const float4*)pA       : make_float4(0,0,0,0);
        float4 v1 = okA ? *(const float4*)(pA + 4) : make_float4(0,0,0,0);
        aReg[0]=v0.x; aReg[1]=v0.y; aReg[2]=v0.z; aReg[3]=v0.w;
        aReg[4]=v1.x; aReg[5]=v1.y; aReg[6]=v1.z; aReg[7]=v1.w;
        bool okB = (colBase + bCol) < Nc;
        const float* pB = B + (size_t)bRow * Nc + colBase + bCol;
        float4 w0 = okB ? *(const float4*)pB       : make_float4(0,0,0,0);
        float4 w1 = okB ? *(const float4*)(pB + 4) : make_float4(0,0,0,0);
        bReg[0]=w0.x; bReg[1]=w0.y; bReg[2]=w0.z; bReg[3]=w0.w;
        bReg[4]=w1.x; bReg[5]=w1.y; bReg[6]=w1.z; bReg[7]=w1.w;
    }
#pragma unroll
    for (int j = 0; j < 8; j++) As[0][aRow][aK + j]  = f2tf32(aReg[j]);
#pragma unroll
    for (int j = 0; j < 8; j++) Bs[0][bRow][bCol + j] = f2tf32(bReg[j]);
    __syncthreads();

    for (int kt = 0; kt < NT; kt++) {
        int buf = kt & 1;
        if (kt + 1 < NT) {
            bool okA = (rowBase + aRow) < M;
            const float* pA = A + (size_t)(rowBase + aRow) * K + (kt + 1) * GBK + aK;
            float4 v0 = okA ? *(const float4*)pA       : make_float4(0,0,0,0);
            float4 v1 = okA ? *(const float4*)(pA + 4) : make_float4(0,0,0,0);
            aReg[0]=v0.x; aReg[1]=v0.y; aReg[2]=v0.z; aReg[3]=v0.w;
            aReg[4]=v1.x; aReg[5]=v1.y; aReg[6]=v1.z; aReg[7]=v1.w;
            bool okB = (colBase + bCol) < Nc;
            const float* pB = B + (size_t)((kt + 1) * GBK + bRow) * Nc + colBase + bCol;
            float4 w0 = okB ? *(const float4*)pB       : make_float4(0,0,0,0);
            float4 w1 = okB ? *(const float4*)(pB + 4) : make_float4(0,0,0,0);
            bReg[0]=w0.x; bReg[1]=w0.y; bReg[2]=w0.z; bReg[3]=w0.w;
            bReg[4]=w1.x; bReg[5]=w1.y; bReg[6]=w1.z; bReg[7]=w1.w;
        }
#pragma unroll
        for (int ks = 0; ks < 2; ks++) {
            int kb = ks * 8;
            uint32_t af[4][4], bf[4][2];
#pragma unroll
            for (int mt = 0; mt < 4; mt++) {
                int r = wr * 64 + mt * 16 + lr;
                af[mt][0] = As[buf][r    ][kb + lc];
                af[mt][1] = As[buf][r + 8][kb + lc];
                af[mt][2] = As[buf][r    ][kb + lc + 4];
                af[mt][3] = As[buf][r + 8][kb + lc + 4];
            }
#pragma unroll
            for (int nt = 0; nt < 4; nt++) {
                int c = wc * 32 + nt * 8 + lr;
                bf[nt][0] = Bs[buf][kb + lc    ][c];
                bf[nt][1] = Bs[buf][kb + lc + 4][c];
            }
#pragma unroll
            for (int mt = 0; mt < 4; mt++)
#pragma unroll
                for (int nt = 0; nt < 4; nt++)
                    mma_tf32(acc[mt][nt], af[mt], bf[nt]);
        }
        if (kt + 1 < NT) {
            int nb2 = 1 - buf;
#pragma unroll
            for (int j = 0; j < 8; j++) As[nb2][aRow][aK + j]  = f2tf32(aReg[j]);
#pragma unroll
            for (int j = 0; j < 8; j++) Bs[nb2][bRow][bCol + j] = f2tf32(bReg[j]);
        }
        __syncthreads();
    }

#pragma unroll
    for (int nt = 0; nt < 4; nt++) {
        int col = colBase + wc * 32 + nt * 8 + 2 * lc;
        if (col >= Nc) continue;
        float2 bb = make_float2(0.f, 0.f);
        if (BIAS) bb = *(const float2*)&bias[col];
#pragma unroll
        for (int mt = 0; mt < 4; mt++) {
            int row = rowBase + wr * 64 + mt * 16 + lr;
#pragma unroll
            for (int half = 0; half < 2; half++) {
                int rr = row + half * 8;
                if (rr < M) {
                    float ox = acc[mt][nt][half * 2]     + bb.x;
                    float oy = acc[mt][nt][half * 2 + 1] + bb.y;
                    if (RELU) { ox = fmaxf(ox, 0.f); oy = fmaxf(oy, 0.f); }
                    float2 o;
                    if (ROUND) {
                        o.x = __uint_as_float(f2tf32(ox));
                        o.y = __uint_as_float(f2tf32(oy));
                    } else { o.x = ox; o.y = oy; }
                    *(float2*)&C[(size_t)rr * Nc + col] = o;
                }
            }
        }
    }
}

// ---------------- fused 3-GEMM, cp.async pipeline, GBK=32 -------------------
// grid: (6 segments, 782 row tiles) — segments on X so a wave covers all 6
// segments of adjacent row tiles -> A is fetched from DRAM once, L2 5x.
#define GBK3 32
#define ST 3
#define ASTR 36
#define BSTR 136
#define SMEM3 ((ST * GBM * ASTR + ST * GBK3 * BSTR) * 4)

__global__ void __launch_bounds__(256, 2) k_mma3a(
    const float* __restrict__ A,
    const float* __restrict__ Wh, const float* __restrict__ bh,
    const float* __restrict__ Wg,
    const float* __restrict__ Wl, const float* __restrict__ bl,
    float* __restrict__ h, float* __restrict__ hg, float* __restrict__ xl)
{
    extern __shared__ float sm[];
    float* As = sm;                              // [ST][128][ASTR]
    float* Bs = sm + ST * GBM * ASTR;            // [ST][32][BSTR]
    uint32_t sbA = (uint32_t)__cvta_generic_to_shared(sm);
    uint32_t sbB = sbA + ST * GBM * ASTR * 4;

    int tid  = threadIdx.x;
    int lane = tid & 31;
    int warp = tid >> 5;
    int wr = warp >> 2, wc = warp & 3;
    int lr = lane >> 2, lc = lane & 3;
    int rowBase = blockIdx.y * GBM;
    int seg = blockIdx.x >> 1;
    int colBase = (blockIdx.x & 1) * GBN;
    const float* B = (seg == 0) ? Wh : (seg == 1 ? Wg : Wl);

    int aRow = tid >> 1;            // 0..127
    int aK   = (tid & 1) * 16;      // 0 or 16
    int bK   = tid >> 3;            // 0..31
    int bCol = (tid & 7) * 16;      // 0..112
    bool okA = (rowBase + aRow) < NN;

    float acc[4][4][4];
#pragma unroll
    for (int m = 0; m < 4; m++)
#pragma unroll
        for (int n = 0; n < 4; n++)
#pragma unroll
            for (int r = 0; r < 4; r++) acc[m][n][r] = 0.f;

    const float* gAbase = A + (size_t)(rowBase + aRow) * DD + aK;
    const float* gBbase = B + (size_t)bK * DD + colBase + bCol;

#define ISSUE(kt, s)                                                            \
    do {                                                                        \
        const float* gA = gAbase + (kt) * GBK3;                                 \
        uint32_t sa = sbA + (((s) * GBM + aRow) * ASTR + aK) * 4;               \
        cpa16(sa,      gA,      okA);                                           \
        cpa16(sa + 16, gA + 4,  okA);                                           \
        cpa16(sa + 32, gA + 8,  okA);                                           \
        cpa16(sa + 48, gA + 12, okA);                                           \
        const float* gB = gBbase + (size_t)(kt) * GBK3 * DD;                    \
        uint32_t sb = sbB + (((s) * GBK3 + bK) * BSTR + bCol) * 4;              \
        cpa16(sb,      gB,      true);                                          \
        cpa16(sb + 16, gB + 4,  true);                                          \
        cpa16(sb + 32, gB + 8,  true);                                          \
        cpa16(sb + 48, gB + 12, true);                                          \
        CP_COMMIT();                                                            \
    } while (0)

    ISSUE(0, 0);
    ISSUE(1, 1);

    const int NT = DD / GBK3;   // 8
    for (int kt = 0; kt < NT; kt++) {
        CP_WAIT1();
        __syncthreads();
        if (kt + 2 < NT) {
            int s2 = (kt + 2) % ST;
            ISSUE(kt + 2, s2);
        } else {
            CP_COMMIT();   // empty group keeps wait_group accounting draining
        }
        int s = kt % ST;
        const float* as = As + s * GBM * ASTR;
        const float* bs = Bs + s * GBK3 * BSTR;
#pragma unroll
        for (int ks = 0; ks < 4; ks++) {
            int kb = ks * 8;
            uint32_t af[4][4], bf[4][2];
#pragma unroll
            for (int mt = 0; mt < 4; mt++) {
                int r = wr * 64 + mt * 16 + lr;
                af[mt][0] = __float_as_uint(as[r * ASTR + kb + lc]);
                af[mt][1] = __float_as_uint(as[(r + 8) * ASTR + kb + lc]);
                af[mt][2] = __float_as_uint(as[r * ASTR + kb + lc + 4]);
                af[mt][3] = __float_as_uint(as[(r + 8) * ASTR + kb + lc + 4]);
            }
#pragma unroll
            for (int nt = 0; nt < 4; nt++) {
                int c = wc * 32 + nt * 8 + lr;
                bf[nt][0] = __float_as_uint(bs[(kb + lc) * BSTR + c]);
                bf[nt][1] = __float_as_uint(bs[(kb + lc + 4) * BSTR + c]);
            }
#pragma unroll
            for (int mt = 0; mt < 4; mt++)
#pragma unroll
                for (int nt = 0; nt < 4; nt++)
                    mma_tf32(acc[mt][nt], af[mt], bf[nt]);
        }
    }
#undef ISSUE

    // epilogue
    bool relu = (seg == 0);
    bool hasBias = (seg != 1);
    const float* bias = (seg == 0) ? bh : bl;
    float* C = (seg == 0) ? h : (seg == 1 ? hg : xl);
#pragma unroll
    for (int nt = 0; nt < 4; nt++) {
        int col = colBase + wc * 32 + nt * 8 + 2 * lc;
        float2 bb = make_float2(0.f, 0.f);
        if (hasBias) bb = *(const float2*)&bias[col];
#pragma unroll
        for (int mt = 0; mt < 4; mt++) {
            int row = rowBase + wr * 64 + mt * 16 + lr;
#pragma unroll
            for (int half = 0; half < 2; half++) {
                int rr = row + half * 8;
                if (rr < NN) {
                    float2 o;
                    o.x = acc[mt][nt][half * 2]     + bb.x;
                    o.y = acc[mt][nt][half * 2 + 1] + bb.y;
                    if (relu) { o.x = fmaxf(o.x, 0.f); o.y = fmaxf(o.y, 0.f); }
                    *(float2*)&C[(size_t)rr * DD + col] = o;
                }
            }
        }
    }
}

// ---------------- attention scalars: a_src/a_dst [N,H] ----------------------
__global__ void k_attn(const float* __restrict__ ws, const float* __restrict__ wd) {
    int w = (blockIdx.x * blockDim.x + threadIdx.x) >> 5;
    int lane = threadIdx.x & 31;
    if (w >= NN * HH) return;
    int n = w >> 2, h = w & 3;
    float2 v = *(const float2*)&g_hg[(size_t)n * DD + h * 64 + lane * 2];
    float2 a = *(const float2*)&ws[h * 64 + lane * 2];
    float2 b = *(const float2*)&wd[h * 64 + lane * 2];
    float ps = v.x * a.x + v.y * a.y;
    float pd = v.x * b.x + v.y * b.y;
#pragma unroll
    for (int o = 16; o; o >>= 1) {
        ps += __shfl_xor_sync(0xFFFFFFFFu, ps, o);
        pd += __shfl_xor_sync(0xFFFFFFFFu, pd, o);
    }
    if (lane == 0) { g_asrc[n * 4 + h] = ps; g_adst[n * 4 + h] = pd; }
}

// ---------------- GAT + combine fused: warp per node ------------------------
__device__ __forceinline__ float pick4(float4 v, int h) {
    float r = v.x;
    r = (h == 1) ? v.y : r;
    r = (h == 2) ? v.z : r;
    r = (h == 3) ? v.w : r;
    return r;
}

__global__ void __launch_bounds__(256) k_gatc(
    const float* __restrict__ bg, const float* __restrict__ lng,
    const float* __restrict__ lnb, const float* __restrict__ betas, int first)
{
    int w = (blockIdx.x * blockDim.x + threadIdx.x) >> 5;
    int lane = threadIdx.x & 31;
    if (w >= NN) return;
    int n = w;
    int h = lane >> 3;
    int colb = lane * 8;

    int beg = g_rowptr[n], end = g_rowptr[n + 1];
    float4 ad4 = *(const float4*)&g_adst[n * 4];
    float adv = pick4(ad4, h);

    float m = -1e30f, s = 0.f;
    float4 acc0 = make_float4(0,0,0,0), acc1 = make_float4(0,0,0,0);

    for (int e = beg; e < end; e++) {
        int src = g_srcs[e];
        float4 as4 = *(const float4*)&g_asrc[src * 4];
        float ev = pick4(as4, h) + adv;
        ev = ev > 0.f ? ev : NEG_SLOPE * ev;
        float nm = fmaxf(m, ev);
        float sc = __expf(m - nm);
        float wg = __expf(ev - nm);
        m = nm;
        s = fmaf(s, sc, wg);
        const float4* hv = (const float4*)&g_hg[(size_t)src * DD + colb];
        float4 v0 = hv[0], v1 = hv[1];
        acc0.x = fmaf(wg, v0.x, acc0.x * sc);
        acc0.y = fmaf(wg, v0.y, acc0.y * sc);
        acc0.z = fmaf(wg, v0.z, acc0.z * sc);
        acc0.w = fmaf(wg, v0.w, acc0.w * sc);
        acc1.x = fmaf(wg, v1.x, acc1.x * sc);
        acc1.y = fmaf(wg, v1.y, acc1.y * sc);
        acc1.z = fmaf(wg, v1.z, acc1.z * sc);
        acc1.w = fmaf(wg, v1.w, acc1.w * sc);
    }
    float inv = 1.f / s;
    size_t idx = (size_t)n * DD + colb;
    float4 b0 = *(const float4*)&bg[colb];
    float4 b1 = *(const float4*)&bg[colb + 4];
    float4 x0 = *(const float4*)&g_xl[idx];
    float4 x1 = *(const float4*)&g_xl[idx + 4];

    float xn[8];
    xn[0] = fmaxf(fmaf(acc0.x, inv, b0.x + x0.x), 0.f);
    xn[1] = fmaxf(fmaf(acc0.y, inv, b0.y + x0.y), 0.f);
    xn[2] = fmaxf(fmaf(acc0.z, inv, b0.z + x0.z), 0.f);
    xn[3] = fmaxf(fmaf(acc0.w, inv, b0.w + x0.w), 0.f);
    xn[4] = fmaxf(fmaf(acc1.x, inv, b1.x + x1.x), 0.f);
    xn[5] = fmaxf(fmaf(acc1.y, inv, b1.y + x1.y), 0.f);
    xn[6] = fmaxf(fmaf(acc1.z, inv, b1.z + x1.z), 0.f);
    xn[7] = fmaxf(fmaf(acc1.w, inv, b1.w + x1.w), 0.f);

    // ---- fused combine: x = (1-beta)*LN(h*xn) + beta*xn ; xloc += x ----
    float4 h0 = *(const float4*)&g_h[idx];
    float4 h1 = *(const float4*)&g_h[idx + 4];
    float t[8] = {h0.x * xn[0], h0.y * xn[1], h0.z * xn[2], h0.w * xn[3],
                  h1.x * xn[4], h1.y * xn[5], h1.z * xn[6], h1.w * xn[7]};

    float sum = 0.f, sq = 0.f;
#pragma unroll
    for (int i = 0; i < 8; i++) { sum += t[i]; sq += t[i] * t[i]; }
#pragma unroll
    for (int o = 16; o; o >>= 1) {
        sum += __shfl_xor_sync(0xFFFFFFFFu, sum, o);
        sq  += __shfl_xor_sync(0xFFFFFFFFu, sq,  o);
    }
    float mean = sum * (1.f / DD);
    float var = sq * (1.f / DD) - mean * mean;
    float rs = rsqrtf(var + LNEPS);

    float4 lg0 = *(const float4*)&lng[colb];
    float4 lg1 = *(const float4*)&lng[colb + 4];
    float4 lb0 = *(const float4*)&lnb[colb];
    float4 lb1 = *(const float4*)&lnb[colb + 4];
    float4 be0 = *(const float4*)&betas[colb];
    float4 be1 = *(const float4*)&betas[colb + 4];
    float lg[8] = {lg0.x, lg0.y, lg0.z, lg0.w, lg1.x, lg1.y, lg1.z, lg1.w};
    float lb[8] = {lb0.x, lb0.y, lb0.z, lb0.w, lb1.x, lb1.y, lb1.z, lb1.w};
    float bev[8] = {be0.x, be0.y, be0.z, be0.w, be1.x, be1.y, be1.z, be1.w};

    float out[8];
#pragma unroll
    for (int i = 0; i < 8; i++) {
        float ln = (t[i] - mean) * rs * lg[i] + lb[i];
        float be = 1.f / (1.f + __expf(-bev[i]));
        out[i] = (1.f - be) * ln + be * xn[i];
    }

    // g_x rounded to tf32 (next GEMM input); xloc full precision
    float4 r0, r1;
    r0.x = __uint_as_float(f2tf32(out[0]));
    r0.y = __uint_as_float(f2tf32(out[1]));
    r0.z = __uint_as_float(f2tf32(out[2]));
    r0.w = __uint_as_float(f2tf32(out[3]));
    r1.x = __uint_as_float(f2tf32(out[4]));
    r1.y = __uint_as_float(f2tf32(out[5]));
    r1.z = __uint_as_float(f2tf32(out[6]));
    r1.w = __uint_as_float(f2tf32(out[7]));
    *(float4*)&g_x[idx]     = r0;
    *(float4*)&g_x[idx + 4] = r1;

    float4 o0 = make_float4(out[0], out[1], out[2], out[3]);
    float4 o1 = make_float4(out[4], out[5], out[6], out[7]);
    if (first) {
        *(float4*)&g_xloc[idx]     = o0;
        *(float4*)&g_xloc[idx + 4] = o1;
    } else {
        float4 l0 = *(float4*)&g_xloc[idx];
        float4 l1 = *(float4*)&g_xloc[idx + 4];
        l0.x += o0.x; l0.y += o0.y; l0.z += o0.z; l0.w += o0.w;
        l1.x += o1.x; l1.y += o1.y; l1.z += o1.z; l1.w += o1.w;
        *(float4*)&g_xloc[idx]     = l0;
        *(float4*)&g_xloc[idx + 4] = l1;
    }
}

// ---------------- driver -----------------------------------------------------
extern "C" void kernel_launch(void* const* d_in, const int* in_sizes, int n_in,
                              void* d_out, int out_size) {
    const float* x_in   = (const float*)d_in[0];
    const int*   ei     = (const int*)  d_in[1];
    const float* Win    = (const float*)d_in[2];
    const float* b_in   = (const float*)d_in[3];
    const float* Wh     = (const float*)d_in[4];
    const float* bh     = (const float*)d_in[5];
    const float* Wg     = (const float*)d_in[6];
    const float* attS   = (const float*)d_in[7];
    const float* attD   = (const float*)d_in[8];
    const float* bg     = (const float*)d_in[9];
    const float* Wl     = (const float*)d_in[10];
    const float* bl     = (const float*)d_in[11];
    const float* lng    = (const float*)d_in[12];
    const float* lnb    = (const float*)d_in[13];
    const float* betas  = (const float*)d_in[14];
    const float* Wp     = (const float*)d_in[15];
    const float* bp     = (const float*)d_in[16];
    float* out = (float*)d_out;

    cudaFuncSetAttribute(k_mma3a, cudaFuncAttributeMaxDynamicSharedMemorySize, SMEM3);

    float* px;   cudaGetSymbolAddress((void**)&px,   g_x);
    float* ph;   cudaGetSymbolAddress((void**)&ph,   g_h);
    float* phg;  cudaGetSymbolAddress((void**)&phg,  g_hg);
    float* pxl;  cudaGetSymbolAddress((void**)&pxl,  g_xl);
    float* pxlo; cudaGetSymbolAddress((void**)&pxlo, g_xloc);
    float* pwr;  cudaGetSymbolAddress((void**)&pwr,  g_wr);

    const float* rWh = pwr;
    const float* rWg = pwr + 196608;
    const float* rWl = pwr + 393216;

    dim3 gA(DD / GBN, cdiv(NN, GBM));   // (2, 782): cols on x, rows on y
    dim3 gF(6, cdiv(NN, GBM));          // (6, 782): segments on x

    // 1: weight pre-round, 2: input GEMM, 3: init, 4: layer-0 fused GEMM (ncu)
    k_round<<<cdiv(147456, 256), 256>>>(Wh, Wg, Wl);
    k_mma<false, true, true><<<gA, 256>>>(x_in, Win, b_in, px, NN, DD, DD);
    k_init_cnt<<<cdiv(NN, 256), 256>>>();
    k_mma3a<<<gF, 256, SMEM3>>>(px, rWh, bh, rWg, rWl, bl, ph, phg, pxl);

    // CSR build
    k_hist<<<cdiv(EE, 256), 256>>>(ei);
    int nb = cdiv(NN, 1024);
    k_scan1<<<nb, 1024>>>();
    k_scan2<<<1, 32>>>(nb);
    k_scan3<<<cdiv(NN, 256), 256>>>();
    k_scatter<<<cdiv(EE + NN, 256), 256>>>(ei);

    for (int i = 0; i < 3; i++) {
        if (i > 0) {
            k_mma3a<<<gF, 256, SMEM3>>>(px, rWh + i * 65536, bh + i * DD,
                                        rWg + i * 65536, rWl + i * 65536, bl + i * DD,
                                        ph, phg, pxl);
        }
        k_attn<<<cdiv(NN * HH * 32, 256), 256>>>(attS + i * DD, attD + i * DD);
        k_gatc<<<cdiv(NN * 32, 256), 256>>>(bg + i * DD, lng + i * DD,
                                            lnb + i * DD, betas + i * DD, i == 0);
    }

    // out = xloc @ Wp + bp
    dim3 gO(1, cdiv(NN, GBM));
    k_mma<false, true, false><<<gO, 256>>>(pxlo, Wp, bp, out, NN, DD, OUTD);
}

// round 8
// speedup vs baseline: 1.0832x; 1.0832x over previous
#include <cuda_runtime.h>
#include <cstdint>

// ----------------------------------------------------------------------------
// Polynormer forward: N=100000, E=1.6M, D=256, H=4, C=64, L=3, OUT=64
// R8: fragment loads via ldmatrix.x4 (24 scalar LDS -> 6 LDSM per 8-k group);
//     weights pre-transposed to [n][k] in k_round so B uses the same pattern.
// ----------------------------------------------------------------------------

#define NN 100000
#define EE 1600000
#define DD 256
#define HH 4
#define OUTD 64
#define NEG_SLOPE 0.2f
#define LNEPS 1e-5f

// ---------------- scratch (device globals; allocation-free) -----------------
__device__ float g_x   [NN * DD];
__device__ float g_h   [NN * DD];
__device__ float g_hg  [NN * DD];
__device__ float g_xl  [NN * DD];
__device__ float g_xloc[NN * DD];
__device__ float g_wr  [3 * 196608];      // tf32-rounded, TRANSPOSED [n][k] Wh|Wg|Wl
__device__ float g_asrc[NN * HH];
__device__ float g_adst[NN * HH];
__device__ int   g_cnt   [NN];
__device__ int   g_rowptr[NN + 1];
__device__ int   g_cursor[NN];
__device__ int   g_srcs  [EE + NN];
__device__ int   g_bsum[128];
__device__ int   g_boff[128];

static inline int cdiv(int a, int b) { return (a + b - 1) / b; }

__device__ __forceinline__ uint32_t f2tf32(float f) {
    uint32_t u;
    asm("cvt.rna.tf32.f32 %0, %1;" : "=r"(u) : "f"(f));
    return u;
}

// ---------------- CSR build --------------------------------------------------
__global__ void k_init_cnt() {
    int i = blockIdx.x * blockDim.x + threadIdx.x;
    if (i < NN) g_cnt[i] = 1;  // self loop
}

__global__ void k_hist(const int* __restrict__ ei) {
    int i = blockIdx.x * blockDim.x + threadIdx.x;
    if (i < EE) atomicAdd(&g_cnt[ei[EE + i]], 1);
}

__global__ void k_scan1() {
    __shared__ int sh[1024];
    int t = threadIdx.x, b = blockIdx.x;
    int idx = b * 1024 + t;
    int v = (idx < NN) ? g_cnt[idx] : 0;
    sh[t] = v;
    for (int off = 1; off < 1024; off <<= 1) {
        __syncthreads();
        int u = (t >= off) ? sh[t - off] : 0;
        __syncthreads();
        sh[t] += u;
    }
    if (idx < NN) g_rowptr[idx + 1] = sh[t];
    if (t == 1023) g_bsum[b] = sh[t];
}

__global__ void k_scan2(int nb) {
    if (threadIdx.x == 0 && blockIdx.x == 0) {
        int acc = 0;
        for (int i = 0; i < nb; i++) { g_boff[i] = acc; acc += g_bsum[i]; }
    }
}

__global__ void k_scan3() {
    int idx = blockIdx.x * blockDim.x + threadIdx.x;
    if (idx == 0) { g_rowptr[0] = 0; g_cursor[0] = 0; }
    if (idx < NN) {
        int v = g_rowptr[idx + 1] + g_boff[idx >> 10];
        g_rowptr[idx + 1] = v;
        if (idx + 1 < NN) g_cursor[idx + 1] = v;
    }
}

__global__ void k_scatter(const int* __restrict__ ei) {
    int idx = blockIdx.x * blockDim.x + threadIdx.x;
    int src, dst;
    if (idx < EE)            { src = ei[idx]; dst = ei[EE + idx]; }
    else if (idx < EE + NN)  { src = idx - EE; dst = src; }
    else return;
    int pos = atomicAdd(&g_cursor[dst], 1);
    g_srcs[pos] = src;
}

// ---------------- weight pre-round + transpose to [n][k] --------------------
__global__ void k_round(const float* __restrict__ Wh, const float* __restrict__ Wg,
                        const float* __restrict__ Wl) {
    int t = blockIdx.x * blockDim.x + threadIdx.x;    // float index
    if (t >= 589824) return;                           // 9 matrices of 256x256
    int m = t >> 16;                                   // matrix 0..8
    int o = t & 65535;
    int n = o >> 8, k = o & 255;
    const float* src = (m < 3) ? (Wh + m * 65536)
                     : (m < 6) ? (Wg + (m - 3) * 65536)
                               : (Wl + (m - 6) * 65536);
    float v = src[k * 256 + n];
    g_wr[t] = __uint_as_float(f2tf32(v));
}

// ---------------- MMA primitives ---------------------------------------------
#define GBM 128
#define GBN 128
#define GBK 16

__device__ __forceinline__ void mma_tf32(float* d, const uint32_t* a, const uint32_t* b) {
    asm volatile(
        "mma.sync.aligned.m16n8k8.row.col.f32.tf32.tf32.f32 "
        "{%0,%1,%2,%3}, {%4,%5,%6,%7}, {%8,%9}, {%0,%1,%2,%3};\n"
        : "+f"(d[0]), "+f"(d[1]), "+f"(d[2]), "+f"(d[3])
        : "r"(a[0]), "r"(a[1]), "r"(a[2]), "r"(a[3]), "r"(b[0]), "r"(b[1]));
}

__device__ __forceinline__ void cpa16(uint32_t sa, const void* g, bool p) {
    int sz = p ? 16 : 0;
    asm volatile("cp.async.cg.shared.global [%0], [%1], 16, %2;\n"
                 :: "r"(sa), "l"(g), "r"(sz) : "memory");
}
#define CP_COMMIT() asm volatile("cp.async.commit_group;\n" ::: "memory")
#define CP_WAIT1()  asm volatile("cp.async.wait_group 1;\n" ::: "memory")

#define LDSM4(r0, r1, r2, r3, addr)                                            \
    asm volatile("ldmatrix.sync.aligned.m8n8.x4.shared.b16 {%0,%1,%2,%3}, [%4];" \
                 : "=r"(r0), "=r"(r1), "=r"(r2), "=r"(r3) : "r"(addr))

// ---------------- legacy GEMM (cvt path) for input/output GEMMs --------------
template <bool RELU, bool BIAS, bool ROUND>
__global__ void __launch_bounds__(256, 2) k_mma(
    const float* __restrict__ A, const float* __restrict__ B,
    const float* __restrict__ bias, float* __restrict__ C,
    int M, int K, int Nc)
{
    __shared__ uint32_t As[2][GBM][GBK + 4];
    __shared__ uint32_t Bs[2][GBK][GBN + 8];

    int tid  = threadIdx.x;
    int lane = tid & 31;
    int warp = tid >> 5;
    int wr = warp >> 2, wc = warp & 3;
    int lr = lane >> 2, lc = lane & 3;
    int rowBase = blockIdx.y * GBM;
    int colBase = blockIdx.x * GBN;

    int aRow = tid >> 1;
    int aK   = (tid & 1) << 3;
    int bRow = tid >> 4;
    int bCol = (tid & 15) << 3;

    float acc[4][4][4];
#pragma unroll
    for (int m = 0; m < 4; m++)
#pragma unroll
        for (int n = 0; n < 4; n++)
#pragma unroll
            for (int r = 0; r < 4; r++) acc[m][n][r] = 0.f;

    float aReg[8], bReg[8];
    const int NT = K / GBK;

    {
        bool okA = (rowBase + aRow) < M;
        const float* pA = A + (size_t)(rowBase + aRow) * K + aK;
        float4 v0 = okA ? *(const float4*)pA       : make_float4(0,0,0,0);
        float4 v1 = okA ? *(const float4*)(pA + 4) : make_float4(0,0,0,0);
        aReg[0]=v0.x; aReg[1]=v0.y; aReg[2]=v0.z; aReg[3]=v0.w;
        aReg[4]=v1.x; aReg[5]=v1.y; aReg[6]=v1.z; aReg[7]=v1.w;
        bool okB = (colBase + bCol) < Nc;
        const float* pB = B + (size_t)bRow * Nc + colBase + bCol;
        float4 w0 = okB ? *(const float4*)pB       : make_float4(0,0,0,0);
        float4 w1 = okB ? *(const float4*)(pB + 4) : make_float4(0,0,0,0);
        bReg[0]=w0.x; bReg[1]=w0.y; bReg[2]=w0.z; bReg[3]=w0.w;
        bReg[4]=w1.x; bReg[5]=w1.y; bReg[6]=w1.z; bReg[7]=w1.w;
    }
#pragma unroll
    for (int j = 0; j < 8; j++) As[0][aRow][aK + j]  = f2tf32(aReg[j]);
#pragma unroll
    for (int j = 0; j < 8; j++) Bs[0][bRow][bCol + j] = f2tf32(bReg[j]);
    __syncthreads();

    for (int kt = 0; kt < NT; kt++) {
        int buf = kt & 1;
        if (kt + 1 < NT) {
            bool okA = (rowBase + aRow) < M;
            const float* pA = A + (size_t)(rowBase + aRow) * K + (kt + 1) * GBK + aK;
            float4 v0 = okA ? *(const float4*)pA       : make_float4(0,0,0,0);
            float4 v1 = okA ? *(const float4*)(pA + 4) : make_float4(0,0,0,0);
            aReg[0]=v0.x; aReg[1]=v0.y; aReg[2]=v0.z; aReg[3]=v0.w;
            aReg[4]=v1.x; aReg[5]=v1.y; aReg[6]=v1.z; aReg[7]=v1.w;
            bool okB = (colBase + bCol) < Nc;
            const float* pB = B + (size_t)((kt + 1) * GBK + bRow) * Nc + colBase + bCol;
            float4 w0 = okB ? *(const float4*)pB       : make_float4(0,0,0,0);
            float4 w1 = okB ? *(const float4*)(pB + 4) : make_float4(0,0,0,0);
            bReg[0]=w0.x; bReg[1]=w0.y; bReg[2]=w0.z; bReg[3]=w0.w;
            bReg[4]=w1.x; bReg[5]=w1.y; bReg[6]=w1.z; bReg[7]=w1.w;
        }
#pragma unroll
        for (int ks = 0; ks < 2; ks++) {
            int kb = ks * 8;
            uint32_t af[4][4], bf[4][2];
#pragma unroll
            for (int mt = 0; mt < 4; mt++) {
                int r = wr * 64 + mt * 16 + lr;
                af[mt][0] = As[buf][r    ][kb + lc];
                af[mt][1] = As[buf][r + 8][kb + lc];
                af[mt][2] = As[buf][r    ][kb + lc + 4];
                af[mt][3] = As[buf][r + 8][kb + lc + 4];
            }
#pragma unroll
            for (int nt = 0; nt < 4; nt++) {
                int c = wc * 32 + nt * 8 + lr;
                bf[nt][0] = Bs[buf][kb + lc    ][c];
                bf[nt][1] = Bs[buf][kb + lc + 4][c];
            }
#pragma unroll
            for (int mt = 0; mt < 4; mt++)
#pragma unroll
                for (int nt = 0; nt < 4; nt++)
                    mma_tf32(acc[mt][nt], af[mt], bf[nt]);
        }
        if (kt + 1 < NT) {
            int nb2 = 1 - buf;
#pragma unroll
            for (int j = 0; j < 8; j++) As[nb2][aRow][aK + j]  = f2tf32(aReg[j]);
#pragma unroll
            for (int j = 0; j < 8; j++) Bs[nb2][bRow][bCol + j] = f2tf32(bReg[j]);
        }
        __syncthreads();
    }

#pragma unroll
    for (int nt = 0; nt < 4; nt++) {
        int col = colBase + wc * 32 + nt * 8 + 2 * lc;
        if (col >= Nc) continue;
        float2 bb = make_float2(0.f, 0.f);
        if (BIAS) bb = *(const float2*)&bias[col];
#pragma unroll
        for (int mt = 0; mt < 4; mt++) {
            int row = rowBase + wr * 64 + mt * 16 + lr;
#pragma unroll
            for (int half = 0; half < 2; half++) {
                int rr = row + half * 8;
                if (rr < M) {
                    float ox = acc[mt][nt][half * 2]     + bb.x;
                    float oy = acc[mt][nt][half * 2 + 1] + bb.y;
                    if (RELU) { ox = fmaxf(ox, 0.f); oy = fmaxf(oy, 0.f); }
                    float2 o;
                    if (ROUND) {
                        o.x = __uint_as_float(f2tf32(ox));
                        o.y = __uint_as_float(f2tf32(oy));
                    } else { o.x = ox; o.y = oy; }
                    *(float2*)&C[(size_t)rr * Nc + col] = o;
                }
            }
        }
    }
}

// ---------------- fused 3-GEMM, cp.async + ldmatrix, GBK=32 -----------------
// A[m][k] row-major, B TRANSPOSED [n][k] row-major: identical smem layouts.
#define GBK3 32
#define ST 3
#define TSTR 36                     // row stride (words): (4r+c)%32 conflict-free
#define TILE_W (128 * TSTR)         // words per stage per operand
#define SMEM3 (2 * ST * TILE_W * 4)

__global__ void __launch_bounds__(256, 2) k_mma3a(
    const float* __restrict__ A,
    const float* __restrict__ Wh, const float* __restrict__ bh,
    const float* __restrict__ Wg,
    const float* __restrict__ Wl, const float* __restrict__ bl,
    float* __restrict__ h, float* __restrict__ hg, float* __restrict__ xl)
{
    extern __shared__ float sm[];
    uint32_t sbA = (uint32_t)__cvta_generic_to_shared(sm);
    uint32_t sbB = sbA + ST * TILE_W * 4;

    int tid  = threadIdx.x;
    int lane = tid & 31;
    int warp = tid >> 5;
    int wr = warp >> 2, wc = warp & 3;
    int lr = lane >> 2, lc = lane & 3;
    int rowBase = blockIdx.y * GBM;
    int seg = blockIdx.x >> 1;
    int colBase = (blockIdx.x & 1) * GBN;
    const float* B = (seg == 0) ? Wh : (seg == 1 ? Wg : Wl);

    // cp.async mapping: thread t -> row t>>1 (m or n), k-quarter (t&1)*16
    int row = tid >> 1;
    int kq  = (tid & 1) * 16;
    bool okA = (rowBase + row) < NN;
    const float* gA0 = A + (size_t)(rowBase + row) * DD + kq;
    const float* gB0 = B + (size_t)(colBase + row) * DD + kq;
    uint32_t saBase = ((row * TSTR + kq) * 4);
    // ldmatrix per-lane offsets (words): A rows (l&7)+((l>>3)&1)*8, colw (l>>4)*4
    int aOff = (wr * 64 + (lane & 7) + ((lane >> 3) & 1) * 8) * TSTR + (lane >> 4) * 4;
    int bOff = (wc * 32 + (lane & 7) + (lane >> 4) * 8) * TSTR + ((lane >> 3) & 1) * 4;

    float acc[4][4][4];
#pragma unroll
    for (int m = 0; m < 4; m++)
#pragma unroll
        for (int n = 0; n < 4; n++)
#pragma unroll
            for (int r = 0; r < 4; r++) acc[m][n][r] = 0.f;

#define ISSUE(kt, s)                                                            \
    do {                                                                        \
        const float* gA = gA0 + (kt) * GBK3;                                    \
        uint32_t sa = sbA + (s) * TILE_W * 4 + saBase;                          \
        cpa16(sa,      gA,      okA);                                           \
        cpa16(sa + 16, gA + 4,  okA);                                           \
        cpa16(sa + 32, gA + 8,  okA);                                           \
        cpa16(sa + 48, gA + 12, okA);                                           \
        const float* gB = gB0 + (kt) * GBK3;                                    \
        uint32_t sb = sbB + (s) * TILE_W * 4 + saBase;                          \
        cpa16(sb,      gB,      true);                                          \
        cpa16(sb + 16, gB + 4,  true);                                          \
        cpa16(sb + 32, gB + 8,  true);                                          \
        cpa16(sb + 48, gB + 12, true);                                          \
        CP_COMMIT();                                                            \
    } while (0)

    ISSUE(0, 0);
    ISSUE(1, 1);

    const int NT = DD / GBK3;   // 8
    for (int kt = 0; kt < NT; kt++) {
        CP_WAIT1();
        __syncthreads();
        if (kt + 2 < NT) {
            int s2 = (kt + 2) % ST;
            ISSUE(kt + 2, s2);
        } else {
            CP_COMMIT();   // empty group keeps wait_group accounting draining
        }
        int s = kt % ST;
        uint32_t aS = sbA + s * TILE_W * 4 + aOff * 4;
        uint32_t bS = sbB + s * TILE_W * 4 + bOff * 4;
#pragma unroll
        for (int ks = 0; ks < 4; ks++) {
            uint32_t af[4][4], bf[4][2];
#pragma unroll
            for (int mt = 0; mt < 4; mt++)
                LDSM4(af[mt][0], af[mt][1], af[mt][2], af[mt][3],
                      aS + (mt * 16 * TSTR + ks * 8) * 4);
            LDSM4(bf[0][0], bf[0][1], bf[1][0], bf[1][1], bS + (ks * 8) * 4);
            LDSM4(bf[2][0], bf[2][1], bf[3][0], bf[3][1],
                  bS + (16 * TSTR + ks * 8) * 4);
#pragma unroll
            for (int mt = 0; mt < 4; mt++)
#pragma unroll
                for (int nt = 0; nt < 4; nt++)
                    mma_tf32(acc[mt][nt], af[mt], bf[nt]);
        }
    }
#undef ISSUE

    // epilogue
    bool relu = (seg == 0);
    bool hasBias = (seg != 1);
    const float* bias = (seg == 0) ? bh : bl;
    float* C = (seg == 0) ? h : (seg == 1 ? hg : xl);
#pragma unroll
    for (int nt = 0; nt < 4; nt++) {
        int col = colBase + wc * 32 + nt * 8 + 2 * lc;
        float2 bb = make_float2(0.f, 0.f);
        if (hasBias) bb = *(const float2*)&bias[col];
#pragma unroll
        for (int mt = 0; mt < 4; mt++) {
            int row2 = rowBase + wr * 64 + mt * 16 + lr;
#pragma unroll
            for (int half = 0; half < 2; half++) {
                int rr = row2 + half * 8;
                if (rr < NN) {
                    float2 o;
                    o.x = acc[mt][nt][half * 2]     + bb.x;
                    o.y = acc[mt][nt][half * 2 + 1] + bb.y;
                    if (relu) { o.x = fmaxf(o.x, 0.f); o.y = fmaxf(o.y, 0.f); }
                    *(float2*)&C[(size_t)rr * DD + col] = o;
                }
            }
        }
    }
}

// ---------------- attention scalars: a_src/a_dst [N,H] ----------------------
__global__ void k_attn(const float* __restrict__ ws, const float* __restrict__ wd) {
    int w = (blockIdx.x * blockDim.x + threadIdx.x) >> 5;
    int lane = threadIdx.x & 31;
    if (w >= NN * HH) return;
    int n = w >> 2, h = w & 3;
    float2 v = *(const float2*)&g_hg[(size_t)n * DD + h * 64 + lane * 2];
    float2 a = *(const float2*)&ws[h * 64 + lane * 2];
    float2 b = *(const float2*)&wd[h * 64 + lane * 2];
    float ps = v.x * a.x + v.y * a.y;
    float pd = v.x * b.x + v.y * b.y;
#pragma unroll
    for (int o = 16; o; o >>= 1) {
        ps += __shfl_xor_sync(0xFFFFFFFFu, ps, o);
        pd += __shfl_xor_sync(0xFFFFFFFFu, pd, o);
    }
    if (lane == 0) { g_asrc[n * 4 + h] = ps; g_adst[n * 4 + h] = pd; }
}

// ---------------- GAT + combine fused: warp per node ------------------------
__device__ __forceinline__ float pick4(float4 v, int h) {
    float r = v.x;
    r = (h == 1) ? v.y : r;
    r = (h == 2) ? v.z : r;
    r = (h == 3) ? v.w : r;
    return r;
}

__global__ void __launch_bounds__(256) k_gatc(
    const float* __restrict__ bg, const float* __restrict__ lng,
    const float* __restrict__ lnb, const float* __restrict__ betas, int first)
{
    int w = (blockIdx.x * blockDim.x + threadIdx.x) >> 5;
    int lane = threadIdx.x & 31;
    if (w >= NN) return;
    int n = w;
    int h = lane >> 3;
    int colb = lane * 8;

    int beg = g_rowptr[n], end = g_rowptr[n + 1];
    float4 ad4 = *(const float4*)&g_adst[n * 4];
    float adv = pick4(ad4, h);

    float m = -1e30f, s = 0.f;
    float4 acc0 = make_float4(0,0,0,0), acc1 = make_float4(0,0,0,0);

    for (int e = beg; e < end; e++) {
        int src = g_srcs[e];
        float4 as4 = *(const float4*)&g_asrc[src * 4];
        float ev = pick4(as4, h) + adv;
        ev = ev > 0.f ? ev : NEG_SLOPE * ev;
        float nm = fmaxf(m, ev);
        float sc = __expf(m - nm);
        float wg = __expf(ev - nm);
        m = nm;
        s = fmaf(s, sc, wg);
        const float4* hv = (const float4*)&g_hg[(size_t)src * DD + colb];
        float4 v0 = hv[0], v1 = hv[1];
        acc0.x = fmaf(wg, v0.x, acc0.x * sc);
        acc0.y = fmaf(wg, v0.y, acc0.y * sc);
        acc0.z = fmaf(wg, v0.z, acc0.z * sc);
        acc0.w = fmaf(wg, v0.w, acc0.w * sc);
        acc1.x = fmaf(wg, v1.x, acc1.x * sc);
        acc1.y = fmaf(wg, v1.y, acc1.y * sc);
        acc1.z = fmaf(wg, v1.z, acc1.z * sc);
        acc1.w = fmaf(wg, v1.w, acc1.w * sc);
    }
    float inv = 1.f / s;
    size_t idx = (size_t)n * DD + colb;
    float4 b0 = *(const float4*)&bg[colb];
    float4 b1 = *(const float4*)&bg[colb + 4];
    float4 x0 = *(const float4*)&g_xl[idx];
    float4 x1 = *(const float4*)&g_xl[idx + 4];

    float xn[8];
    xn[0] = fmaxf(fmaf(acc0.x, inv, b0.x + x0.x), 0.f);
    xn[1] = fmaxf(fmaf(acc0.y, inv, b0.y + x0.y), 0.f);
    xn[2] = fmaxf(fmaf(acc0.z, inv, b0.z + x0.z), 0.f);
    xn[3] = fmaxf(fmaf(acc0.w, inv, b0.w + x0.w), 0.f);
    xn[4] = fmaxf(fmaf(acc1.x, inv, b1.x + x1.x), 0.f);
    xn[5] = fmaxf(fmaf(acc1.y, inv, b1.y + x1.y), 0.f);
    xn[6] = fmaxf(fmaf(acc1.z, inv, b1.z + x1.z), 0.f);
    xn[7] = fmaxf(fmaf(acc1.w, inv, b1.w + x1.w), 0.f);

    // ---- fused combine: x = (1-beta)*LN(h*xn) + beta*xn ; xloc += x ----
    float4 h0 = *(const float4*)&g_h[idx];
    float4 h1 = *(const float4*)&g_h[idx + 4];
    float t[8] = {h0.x * xn[0], h0.y * xn[1], h0.z * xn[2], h0.w * xn[3],
                  h1.x * xn[4], h1.y * xn[5], h1.z * xn[6], h1.w * xn[7]};

    float sum = 0.f, sq = 0.f;
#pragma unroll
    for (int i = 0; i < 8; i++) { sum += t[i]; sq += t[i] * t[i]; }
#pragma unroll
    for (int o = 16; o; o >>= 1) {
        sum += __shfl_xor_sync(0xFFFFFFFFu, sum, o);
        sq  += __shfl_xor_sync(0xFFFFFFFFu, sq,  o);
    }
    float mean = sum * (1.f / DD);
    float var = sq * (1.f / DD) - mean * mean;
    float rs = rsqrtf(var + LNEPS);

    float4 lg0 = *(const float4*)&lng[colb];
    float4 lg1 = *(const float4*)&lng[colb + 4];
    float4 lb0 = *(const float4*)&lnb[colb];
    float4 lb1 = *(const float4*)&lnb[colb + 4];
    float4 be0 = *(const float4*)&betas[colb];
    float4 be1 = *(const float4*)&betas[colb + 4];
    float lg[8] = {lg0.x, lg0.y, lg0.z, lg0.w, lg1.x, lg1.y, lg1.z, lg1.w};
    float lb[8] = {lb0.x, lb0.y, lb0.z, lb0.w, lb1.x, lb1.y, lb1.z, lb1.w};
    float bev[8] = {be0.x, be0.y, be0.z, be0.w, be1.x, be1.y, be1.z, be1.w};

    float out[8];
#pragma unroll
    for (int i = 0; i < 8; i++) {
        float ln = (t[i] - mean) * rs * lg[i] + lb[i];
        float be = 1.f / (1.f + __expf(-bev[i]));
        out[i] = (1.f - be) * ln + be * xn[i];
    }

    // g_x rounded to tf32 (next GEMM input); xloc full precision
    float4 r0, r1;
    r0.x = __uint_as_float(f2tf32(out[0]));
    r0.y = __uint_as_float(f2tf32(out[1]));
    r0.z = __uint_as_float(f2tf32(out[2]));
    r0.w = __uint_as_float(f2tf32(out[3]));
    r1.x = __uint_as_float(f2tf32(out[4]));
    r1.y = __uint_as_float(f2tf32(out[5]));
    r1.z = __uint_as_float(f2tf32(out[6]));
    r1.w = __uint_as_float(f2tf32(out[7]));
    *(float4*)&g_x[idx]     = r0;
    *(float4*)&g_x[idx + 4] = r1;

    float4 o0 = make_float4(out[0], out[1], out[2], out[3]);
    float4 o1 = make_float4(out[4], out[5], out[6], out[7]);
    if (first) {
        *(float4*)&g_xloc[idx]     = o0;
        *(float4*)&g_xloc[idx + 4] = o1;
    } else {
        float4 l0 = *(float4*)&g_xloc[idx];
        float4 l1 = *(float4*)&g_xloc[idx + 4];
        l0.x += o0.x; l0.y += o0.y; l0.z += o0.z; l0.w += o0.w;
        l1.x += o1.x; l1.y += o1.y; l1.z += o1.z; l1.w += o1.w;
        *(float4*)&g_xloc[idx]     = l0;
        *(float4*)&g_xloc[idx + 4] = l1;
    }
}

// ---------------- driver -----------------------------------------------------
extern "C" void kernel_launch(void* const* d_in, const int* in_sizes, int n_in,
                              void* d_out, int out_size) {
    const float* x_in   = (const float*)d_in[0];
    const int*   ei     = (const int*)  d_in[1];
    const float* Win    = (const float*)d_in[2];
    const float* b_in   = (const float*)d_in[3];
    const float* Wh     = (const float*)d_in[4];
    const float* bh     = (const float*)d_in[5];
    const float* Wg     = (const float*)d_in[6];
    const float* attS   = (const float*)d_in[7];
    const float* attD   = (const float*)d_in[8];
    const float* bg     = (const float*)d_in[9];
    const float* Wl     = (const float*)d_in[10];
    const float* bl     = (const float*)d_in[11];
    const float* lng    = (const float*)d_in[12];
    const float* lnb    = (const float*)d_in[13];
    const float* betas  = (const float*)d_in[14];
    const float* Wp     = (const float*)d_in[15];
    const float* bp     = (const float*)d_in[16];
    float* out = (float*)d_out;

    cudaFuncSetAttribute(k_mma3a, cudaFuncAttributeMaxDynamicSharedMemorySize, SMEM3);

    float* px;   cudaGetSymbolAddress((void**)&px,   g_x);
    float* ph;   cudaGetSymbolAddress((void**)&ph,   g_h);
    float* phg;  cudaGetSymbolAddress((void**)&phg,  g_hg);
    float* pxl;  cudaGetSymbolAddress((void**)&pxl,  g_xl);
    float* pxlo; cudaGetSymbolAddress((void**)&pxlo, g_xloc);
    float* pwr;  cudaGetSymbolAddress((void**)&pwr,  g_wr);

    const float* rWh = pwr;
    const float* rWg = pwr + 196608;
    const float* rWl = pwr + 393216;

    dim3 gA(DD / GBN, cdiv(NN, GBM));   // (2, 782)
    dim3 gF(6, cdiv(NN, GBM));          // (6, 782)

    // 1: weight pre-round+transpose, 2: input GEMM, 3: init, 4: layer-0 fused GEMM
    k_round<<<cdiv(589824, 256), 256>>>(Wh, Wg, Wl);
    k_mma<false, true, true><<<gA, 256>>>(x_in, Win, b_in, px, NN, DD, DD);
    k_init_cnt<<<cdiv(NN, 256), 256>>>();
    k_mma3a<<<gF, 256, SMEM3>>>(px, rWh, bh, rWg, rWl, bl, ph, phg, pxl);

    // CSR build
    k_hist<<<cdiv(EE, 256), 256>>>(ei);
    int nb = cdiv(NN, 1024);
    k_scan1<<<nb, 1024>>>();
    k_scan2<<<1, 32>>>(nb);
    k_scan3<<<cdiv(NN, 256), 256>>>();
    k_scatter<<<cdiv(EE + NN, 256), 256>>>(ei);

    for (int i = 0; i < 3; i++) {
        if (i > 0) {
            k_mma3a<<<gF, 256, SMEM3>>>(px, rWh + i * 65536, bh + i * DD,
                                        rWg + i * 65536, rWl + i * 65536, bl + i * DD,
                                        ph, phg, pxl);
        }
        k_attn<<<cdiv(NN * HH * 32, 256), 256>>>(attS + i * DD, attD + i * DD);
        k_gatc<<<cdiv(NN * 32, 256), 256>>>(bg + i * DD, lng + i * DD,
                                            lnb + i * DD, betas + i * DD, i == 0);
    }

    // out = xloc @ Wp + bp
    dim3 gO(1, cdiv(NN, GBM));
    k_mma<false, true, false><<<gO, 256>>>(pxlo, Wp, bp, out, NN, DD, OUTD);
}